// round 1
// baseline (speedup 1.0000x reference)
#include <cuda_runtime.h>

// Problem constants
#define HW    128
#define N_SP  16384          // H*W
#define MP    4096           // pooled positions (H/2 * W/2)
#define BATCH 4
#define L2E   1.4426950408889634f

// ---------------- scratch (static device memory; no allocation) ----------------
__device__ float d_theta[BATCH * 8  * N_SP];   // [b][c][n], pre-scaled by log2(e)
__device__ float d_phiF [BATCH * 8  * N_SP];   // full-res phi before pooling
__device__ float d_gF   [BATCH * 32 * N_SP];   // full-res g before pooling
__device__ float d_phiP [BATCH * MP * 8];      // pooled phi, layout [b][m][c]
__device__ float d_gP   [BATCH * MP * 32];     // pooled g,   layout [b][m][c]

// ---------------- packed f32x2 helpers (Blackwell paired-FP32 pipe) ----------------
typedef unsigned long long f2;

__device__ __forceinline__ f2 pack2(float a, float b) {
    f2 r; asm("mov.b64 %0,{%1,%2};" : "=l"(r) : "f"(a), "f"(b)); return r;
}
__device__ __forceinline__ void unpack2(f2 v, float& a, float& b) {
    asm("mov.b64 {%0,%1},%2;" : "=f"(a), "=f"(b) : "l"(v));
}
__device__ __forceinline__ f2 fma2(f2 a, f2 b, f2 c) {
    f2 d; asm("fma.rn.f32x2 %0,%1,%2,%3;" : "=l"(d) : "l"(a), "l"(b), "l"(c)); return d;
}
__device__ __forceinline__ f2 mul2(f2 a, f2 b) {
    f2 d; asm("mul.rn.f32x2 %0,%1,%2;" : "=l"(d) : "l"(a), "l"(b)); return d;
}
__device__ __forceinline__ float ex2(float x) {
    float r; asm("ex2.approx.f32 %0,%1;" : "=f"(r) : "f"(x)); return r;
}

// ================================================================================
// Kernel A1: fused 1x1 convs. One thread per spatial position (per batch).
// Computes theta (8, scaled by log2e), phi_full (8), g_full (32).
// ================================================================================
__global__ void __launch_bounds__(256) kconv(
    const float* __restrict__ x,
    const float* __restrict__ wt,
    const float* __restrict__ wp,
    const float* __restrict__ wg)
{
    __shared__ float ws[64 * 48];   // [c][48]: 0..7 theta, 8..15 phi, 16..47 g
    const int tid = threadIdx.x;

    for (int i = tid; i < 64 * 48; i += 256) {
        int c = i / 48, o = i % 48;
        float v = (o < 8)  ? wt[o * 64 + c]
                : (o < 16) ? wp[(o - 8) * 64 + c]
                           : wg[(o - 16) * 64 + c];
        ws[c * 48 + o] = v;
    }
    __syncthreads();

    const int t = blockIdx.x * 256 + tid;         // 0 .. B*N-1
    const int b = t >> 14;
    const int n = t & (N_SP - 1);
    const float* xb = x + ((size_t)b * 64) * N_SP + n;

    float acc[48];
    #pragma unroll
    for (int o = 0; o < 48; ++o) acc[o] = 0.0f;

    #pragma unroll 4
    for (int c = 0; c < 64; ++c) {
        float xv = xb[(size_t)c * N_SP];
        const float4* w4 = reinterpret_cast<const float4*>(&ws[c * 48]);
        #pragma unroll
        for (int j = 0; j < 12; ++j) {
            float4 w = w4[j];
            acc[4 * j + 0] += w.x * xv;
            acc[4 * j + 1] += w.y * xv;
            acc[4 * j + 2] += w.z * xv;
            acc[4 * j + 3] += w.w * xv;
        }
    }

    #pragma unroll
    for (int o = 0; o < 8; ++o)
        d_theta[((size_t)b * 8 + o) * N_SP + n] = acc[o] * L2E;
    #pragma unroll
    for (int o = 0; o < 8; ++o)
        d_phiF[((size_t)b * 8 + o) * N_SP + n] = acc[8 + o];
    #pragma unroll
    for (int o = 0; o < 32; ++o)
        d_gF[((size_t)b * 32 + o) * N_SP + n] = acc[16 + o];
}

// ================================================================================
// Kernel A2: 2x2 max pool + relayout to [b][m][c] (c contiguous) for kernel B.
// One thread per (b, m).
// ================================================================================
__global__ void __launch_bounds__(256) kpool()
{
    const int t = blockIdx.x * 256 + threadIdx.x;  // 0 .. B*MP-1
    const int b = t >> 12;
    const int m = t & (MP - 1);
    const int i = m >> 6, j = m & 63;
    const int base = (i * 2) * HW + (j * 2);

    float pout[8];
    #pragma unroll
    for (int o = 0; o < 8; ++o) {
        const float* p = &d_phiF[((size_t)b * 8 + o) * N_SP + base];
        float2 r0 = *reinterpret_cast<const float2*>(p);
        float2 r1 = *reinterpret_cast<const float2*>(p + HW);
        pout[o] = fmaxf(fmaxf(r0.x, r0.y), fmaxf(r1.x, r1.y));
    }
    float4* pd = reinterpret_cast<float4*>(&d_phiP[((size_t)b * MP + m) * 8]);
    pd[0] = make_float4(pout[0], pout[1], pout[2], pout[3]);
    pd[1] = make_float4(pout[4], pout[5], pout[6], pout[7]);

    float gout[32];
    #pragma unroll
    for (int o = 0; o < 32; ++o) {
        const float* p = &d_gF[((size_t)b * 32 + o) * N_SP + base];
        float2 r0 = *reinterpret_cast<const float2*>(p);
        float2 r1 = *reinterpret_cast<const float2*>(p + HW);
        gout[o] = fmaxf(fmaxf(r0.x, r0.y), fmaxf(r1.x, r1.y));
    }
    float4* gd = reinterpret_cast<float4*>(&d_gP[((size_t)b * MP + m) * 32]);
    #pragma unroll
    for (int k = 0; k < 8; ++k)
        gd[k] = make_float4(gout[4 * k], gout[4 * k + 1], gout[4 * k + 2], gout[4 * k + 3]);
}

// ================================================================================
// Kernel B: fused flash attention + output projection + residual.
// 128 threads/CTA, 2 queries/thread -> 256 queries/CTA, 64 CTAs/batch, 256 CTAs.
// Online softmax over 4096 keys in 16 tiles of 256. All SMEM reads broadcast.
// ================================================================================
__global__ void __launch_bounds__(128) kattn(
    const float* __restrict__ x,
    const float* __restrict__ wo,
    const float* __restrict__ gamma,
    float* __restrict__ out)
{
    __shared__ float phi_s[256 * 8];    // [i][c] (reused for w_o in epilogue)
    __shared__ float g_s[256 * 32];     // [i][c]

    const int tid   = threadIdx.x;
    const int blk   = blockIdx.x;
    const int b     = blk >> 6;
    const int qbase = (blk & 63) << 8;
    const int q0    = qbase + tid;      // second query: q0 + 128

    // load theta (already scaled by log2e), pack channel pairs
    f2 th[2][4];
    #pragma unroll
    for (int qq = 0; qq < 2; ++qq) {
        const float* tp = &d_theta[((size_t)b * 8) * N_SP + q0 + qq * 128];
        #pragma unroll
        for (int j = 0; j < 4; ++j)
            th[qq][j] = pack2(tp[(size_t)(2 * j) * N_SP], tp[(size_t)(2 * j + 1) * N_SP]);
    }

    f2    acc[2][16];
    float l[2], mx[2];
    #pragma unroll
    for (int qq = 0; qq < 2; ++qq) {
        l[qq] = 0.0f; mx[qq] = -3.0e38f;
        #pragma unroll
        for (int k = 0; k < 16; ++k) acc[qq][k] = 0ULL;
    }

    const float* phiPb = &d_phiP[(size_t)b * MP * 8];
    const float* gPb   = &d_gP[(size_t)b * MP * 32];

    for (int mt = 0; mt < 16; ++mt) {
        // stage tile: phi 256x8 (512 float4), g 256x32 (2048 float4)
        {
            const float4* sp = reinterpret_cast<const float4*>(phiPb + (size_t)mt * 256 * 8);
            float4*       dp = reinterpret_cast<float4*>(phi_s);
            #pragma unroll
            for (int k = 0; k < 4; ++k) dp[tid + 128 * k] = sp[tid + 128 * k];
            const float4* sg = reinterpret_cast<const float4*>(gPb + (size_t)mt * 256 * 32);
            float4*       dg = reinterpret_cast<float4*>(g_s);
            #pragma unroll
            for (int k = 0; k < 16; ++k) dg[tid + 128 * k] = sg[tid + 128 * k];
        }
        __syncthreads();

        #pragma unroll 2
        for (int i = 0; i < 256; ++i) {
            const ulonglong2* pr = reinterpret_cast<const ulonglong2*>(phi_s + i * 8);
            ulonglong2 phA = pr[0];
            ulonglong2 phB = pr[1];

            f2 p2[2];
            #pragma unroll
            for (int qq = 0; qq < 2; ++qq) {
                f2 s2 = mul2(th[qq][0], phA.x);
                s2 = fma2(th[qq][1], phA.y, s2);
                s2 = fma2(th[qq][2], phB.x, s2);
                s2 = fma2(th[qq][3], phB.y, s2);
                float sa, sb; unpack2(s2, sa, sb);
                float s = sa + sb;       // score in log2 domain
                float p;
                if (s > mx[qq]) {        // rare after warmup
                    float corr = ex2(mx[qq] - s);
                    l[qq] *= corr;
                    f2 c2 = pack2(corr, corr);
                    #pragma unroll
                    for (int k = 0; k < 16; ++k) acc[qq][k] = mul2(acc[qq][k], c2);
                    mx[qq] = s;
                    p = 1.0f;
                } else {
                    p = ex2(s - mx[qq]);
                }
                l[qq] += p;
                p2[qq] = pack2(p, p);
            }

            const ulonglong2* gr = reinterpret_cast<const ulonglong2*>(g_s + i * 32);
            #pragma unroll
            for (int k = 0; k < 8; ++k) {
                ulonglong2 gv = gr[k];
                acc[0][2 * k + 0] = fma2(p2[0], gv.x, acc[0][2 * k + 0]);
                acc[0][2 * k + 1] = fma2(p2[0], gv.y, acc[0][2 * k + 1]);
                acc[1][2 * k + 0] = fma2(p2[1], gv.x, acc[1][2 * k + 0]);
                acc[1][2 * k + 1] = fma2(p2[1], gv.y, acc[1][2 * k + 1]);
            }
        }
        __syncthreads();
    }

    // ---------------- epilogue: o = w_o @ (acc / l); out = gamma*o + x ----------------
    {
        // reuse phi_s (2048 floats) for w_o [64][32]
        float4*       wd = reinterpret_cast<float4*>(phi_s);
        const float4* wsrc = reinterpret_cast<const float4*>(wo);
        #pragma unroll
        for (int k = 0; k < 4; ++k) wd[tid + 128 * k] = wsrc[tid + 128 * k];
    }
    __syncthreads();

    const float gammav = gamma[0];
    #pragma unroll
    for (int qq = 0; qq < 2; ++qq) {
        const int q = q0 + qq * 128;
        const float inv = 1.0f / l[qq];
        const float* xq = x   + ((size_t)b * 64) * N_SP + q;
        float*       oq = out + ((size_t)b * 64) * N_SP + q;
        #pragma unroll 4
        for (int k = 0; k < 64; ++k) {
            const ulonglong2* w2 = reinterpret_cast<const ulonglong2*>(phi_s + k * 32);
            f2 o2 = 0ULL;
            #pragma unroll
            for (int j = 0; j < 8; ++j) {
                ulonglong2 wv = w2[j];
                o2 = fma2(acc[qq][2 * j + 0], wv.x, o2);
                o2 = fma2(acc[qq][2 * j + 1], wv.y, o2);
            }
            float oa, ob; unpack2(o2, oa, ob);
            float oval = (oa + ob) * inv;
            oq[(size_t)k * N_SP] = fmaf(gammav, oval, xq[(size_t)k * N_SP]);
        }
    }
}

// ================================================================================
extern "C" void kernel_launch(void* const* d_in, const int* in_sizes, int n_in,
                              void* d_out, int out_size)
{
    const float* x     = (const float*)d_in[0];
    const float* wt    = (const float*)d_in[1];
    const float* wp    = (const float*)d_in[2];
    const float* wg    = (const float*)d_in[3];
    const float* wo    = (const float*)d_in[4];
    const float* gamma = (const float*)d_in[5];
    float* out = (float*)d_out;

    kconv<<<256, 256>>>(x, wt, wp, wg);   // B*N threads
    kpool<<<64, 256>>>();                 // B*MP threads
    kattn<<<256, 128>>>(x, wo, gamma, out);
}